// round 13
// baseline (speedup 1.0000x reference)
#include <cuda_runtime.h>
#include <cstdint>
#include <cstddef>

#define BB   128
#define SEQ  720
#define PRED 336
#define ENC  321
#define DD   512
#define NG   2048           // 4*D
#define XSTR (SEQ*ENC)
#define KXP  328            // ENC padded to 41*8
#define EPAD 384            // ENC padded for W_pred^T tiles
#define NBLK 128            // persistent grid
#define LSTM_SMEM (32768 + 131072)   // Ws strip 32 KB + 16-slice partials 128 KB

// -------- persistent device scratch --------
__device__ float g_WX  [KXP * NG];        // Wih^T gate-interleaved [k][n], n=d*4+gate
__device__ float g_WE  [DD * NG];         // Whh^T gate-interleaved
__device__ float g_WD  [DD * NG];         // decoder (Wih@Wp + Whh)^T gate-interleaved
__device__ float g_WpT2[DD * EPAD];       // W_pred^T padded [k][e]
__device__ float g_bias [NG];
__device__ float g_biasd[NG];
__device__ float g_hT4[4][DD * BB];       // 4-deep rotating hidden state, TRANSPOSED [dim][m]
__device__ float g_xg[(size_t)SEQ * BB * NG];         // precomputed x projections
__device__ float g_hist[(size_t)PRED * BB * DD];      // decoder h_t log ([t][m][dim])

__device__ volatile unsigned g_wflag[NBLK * 32];      // h-write counters, 128 B apart
__device__ volatile unsigned g_gdone[NBLK * 32];      // gemm-read counters, 128 B apart

// -------- packed fp32x2 FMA --------
__device__ __forceinline__ void fma2(float2 &d, float2 a, float2 b) {
    unsigned long long &du = reinterpret_cast<unsigned long long &>(d);
    unsigned long long au  = reinterpret_cast<unsigned long long &>(a);
    unsigned long long bu  = reinterpret_cast<unsigned long long &>(b);
    asm("fma.rn.f32x2 %0, %1, %2, %0;" : "+l"(du) : "l"(au), "l"(bu));
}

__device__ __forceinline__ float sigm(float x) { return 1.f / (1.f + __expf(-x)); }

// -------- GEMM micro-kernel pieces (xg_proj / final_pred) --------
struct Slots { int klp[4], mmp[4], kwp[4], nlp[4]; };

__device__ __forceinline__ void make_slots(Slots &s, int tid) {
#pragma unroll
    for (int p = 0; p < 4; ++p) {
        int lin = tid + p * 256;
        s.klp[p] = lin & 7;   s.mmp[p] = lin >> 3;
        s.nlp[p] = lin & 127; s.kwp[p] = lin >> 7;
    }
}

__device__ __forceinline__ void stage(const Slots &s, const float *ur, const float *wr,
                                      float *U, float *W) {
#pragma unroll
    for (int p = 0; p < 4; ++p) {
        U[s.klp[p] * 132 + s.mmp[p]] = ur[p];
        W[s.kwp[p] * 128 + s.nlp[p]] = wr[p];
    }
}

__device__ __forceinline__ void mma8(float2 acc[8][4], const float *U, const float *W,
                                     int tm8, int tn8) {
#pragma unroll
    for (int q = 0; q < 8; ++q) {
        const float4 a0 = *(const float4 *)&U[q * 132 + tm8];
        const float4 a1 = *(const float4 *)&U[q * 132 + tm8 + 4];
        const float4 b0 = *(const float4 *)&W[q * 128 + tn8];
        const float4 b1 = *(const float4 *)&W[q * 128 + tn8 + 4];
        float  av[8] = {a0.x, a0.y, a0.z, a0.w, a1.x, a1.y, a1.z, a1.w};
        float2 bv[4] = {make_float2(b0.x, b0.y), make_float2(b0.z, b0.w),
                        make_float2(b1.x, b1.y), make_float2(b1.z, b1.w)};
#pragma unroll
        for (int r = 0; r < 8; ++r) {
            float2 ad = make_float2(av[r], av[r]);
#pragma unroll
            for (int c = 0; c < 4; ++c) fma2(acc[r][c], ad, bv[c]);
        }
    }
}

// ==================== prep kernels ====================
__global__ void prepA(const float *__restrict__ Wih, const float *__restrict__ Whh,
                      const float *__restrict__ bih, const float *__restrict__ bhh,
                      const float *__restrict__ Wp)
{
    int idx = blockIdx.x * 256 + threadIdx.x;
    if (idx < KXP * NG) {
        int k = idx / NG, n = idx - k * NG, d = n >> 2, gate = n & 3, j = gate * DD + d;
        g_WX[idx] = (k < ENC) ? Wih[(size_t)j * ENC + k] : 0.f;
    }
    if (idx < DD * NG) {
        int k = idx / NG, n = idx - k * NG, d = n >> 2, gate = n & 3, j = gate * DD + d;
        g_WE[idx] = Whh[(size_t)j * DD + k];
    }
    if (idx < DD * EPAD) {
        int k = idx / EPAD, e = idx - k * EPAD;
        g_WpT2[idx] = (e < ENC) ? Wp[(size_t)e * DD + k] : 0.f;
    }
    if (idx < NG) {
        int j = idx, n = (j & 511) * 4 + (j >> 9);
        g_bias[n] = bih[j] + bhh[j];
    }
    if (idx < 4 * BB * DD) ((float *)g_hT4)[idx] = 0.f;
    if (idx < NBLK * 32) { g_wflag[idx] = 0; g_gdone[idx] = 0; }   // graph-replay safe
}

// g_WD[k][n] = sum_e Wih[j][e]*Wp[e][k] + Whh[j][k];  biasd[n] = bias[n] + Wih[j]·bp
__global__ void prepB(const float *__restrict__ Wih, const float *__restrict__ Whh,
                      const float *__restrict__ bp)
{
    __shared__ float sW[EPAD];
    __shared__ float red[128];
    const int j = blockIdx.x, tid = threadIdx.x;
    for (int e = tid; e < EPAD; e += 128) sW[e] = (e < ENC) ? Wih[(size_t)j * ENC + e] : 0.f;
    __syncthreads();
    const int d = j & 511, gate = j >> 9, n = d * 4 + gate;
    for (int k = tid; k < DD; k += 128) {
        float a0 = 0.f, a1 = 0.f, a2 = 0.f, a3 = 0.f;
        const float *wr = &g_WpT2[(size_t)k * EPAD];
        for (int e = 0; e < EPAD; e += 4) {
            const float4 wv = *(const float4 *)&wr[e];
            const float4 sv = *(const float4 *)&sW[e];
            a0 += sv.x * wv.x; a1 += sv.y * wv.y; a2 += sv.z * wv.z; a3 += sv.w * wv.w;
        }
        g_WD[(size_t)k * NG + n] = (a0 + a1) + (a2 + a3) + Whh[(size_t)j * DD + k];
    }
    float p = 0.f;
    for (int e = tid; e < ENC; e += 128) p += sW[e] * bp[e];
    red[tid] = p; __syncthreads();
    for (int off = 64; off; off >>= 1) { if (tid < off) red[tid] += red[tid + off]; __syncthreads(); }
    if (tid == 0) g_biasd[n] = g_bias[n] + red[0];
}

// ==================== parallel input projection: xg[t][b][n] ====================
__global__ __launch_bounds__(256) void xg_proj(const float *__restrict__ x)
{
    __shared__ float Us[2][8 * 132];
    __shared__ float Ws[2][8 * 128];
    const int t = blockIdx.y, nbase = blockIdx.x * 128, tid = threadIdx.x;
    const int tm8 = (tid >> 4) * 8, tn8 = (tid & 15) * 8;
    const float *xbase = x + (size_t)t * ENC;

    Slots s; make_slots(s, tid);
    float2 acc[8][4];
#pragma unroll
    for (int r = 0; r < 8; ++r)
#pragma unroll
        for (int c = 0; c < 4; ++c) acc[r][c] = make_float2(0.f, 0.f);

    float ur[4], wr[4];
    auto load = [&](int kb) {
#pragma unroll
        for (int p = 0; p < 4; ++p) {
            int k = kb + s.klp[p];
            ur[p] = (k < ENC) ? __ldg(&xbase[(size_t)s.mmp[p] * XSTR + k]) : 0.f;
            wr[p] = g_WX[(size_t)(kb + s.kwp[p]) * NG + nbase + s.nlp[p]];
        }
    };

    int buf = 0;
    load(0);
    stage(s, ur, wr, Us[0], Ws[0]);
    __syncthreads();
#pragma unroll 1
    for (int c8 = 0; c8 < 41; ++c8) {
        if (c8 < 40) load((c8 + 1) * 8);
        mma8(acc, Us[buf], Ws[buf], tm8, tn8);
        if (c8 < 40) { stage(s, ur, wr, Us[buf ^ 1], Ws[buf ^ 1]); __syncthreads(); buf ^= 1; }
    }
#pragma unroll
    for (int r = 0; r < 8; ++r) {
        float *dst = &g_xg[((size_t)t * BB + tm8 + r) * NG + nbase + tn8];
        *(float4 *)dst       = make_float4(acc[r][0].x, acc[r][0].y, acc[r][1].x, acc[r][1].y);
        *(float4 *)(dst + 4) = make_float4(acc[r][2].x, acc[r][2].y, acc[r][3].x, acc[r][3].y);
    }
}

// ==================== persistent recurrent kernel (dataflow-synced) ====================
// 128 blocks x 512 threads (16 warps). Block bx owns gate-cols [16bx,16bx+16)
// == dims [4bx,4bx+4). Warp w owns k-slice [32w,32w+32); lane L covers batches
// 4L..4L+4 (float4 straight from transposed h in L2). Partials [16][128][16]
// (128 KB smem) reduced once; each thread owns one cell, c in a register.
// Sync: per-warp wait on its 8 producers' wflag (read side); 4-deep h rotation
// + gdone wait with 3-step slack (write side). NO full-grid barrier.
__global__ __launch_bounds__(512, 1) void lstm_persistent()
{
    extern __shared__ float dsm[];
    float *Ws   = dsm;                  // [512][16]  weight strip, 32 KB
    float *part = dsm + DD * 16;        // [16][128][16] partials, 128 KB

    const int tid = threadIdx.x, bx = blockIdx.x;
    const int w = tid >> 5, lane = tid & 31;
    const int k0 = 32 * w;
    const int dl = tid >> 7;            // 0..3  (cell dim within block)
    const int mo = tid & 127;           // cell batch

    // step-invariant addressing
    const int aoff = k0 * 32 + lane;    // float4 units: row k = 32 float4
    float *stp[4];
    int    ssw[4];
#pragma unroll
    for (int i = 0; i < 4; ++i) {
        int mp = 4 * lane + i;
        ssw[i] = ((mp >> 1) ^ (mp >> 2)) & 3;
        stp[i] = &part[w * 2048 + mp * 16];
    }
    const float *rptr = &part[mo * 16 + (dl ^ (((mo >> 1) ^ (mo >> 2)) & 3)) * 4];

    for (int i = tid; i < DD * 16; i += 512)
        Ws[i] = g_WE[(size_t)(i >> 4) * NG + bx * 16 + (i & 15)];
    float4 bias = *(const float4 *)&g_bias[bx * 16 + 4 * dl];
    float cst = 0.f;
    __syncthreads();

    for (int st = 0; st < SEQ + PRED - 1; ++st) {
        const bool enc = (st < SEQ);
        if (st == SEQ) {                 // switch to decoder weights
            for (int i = tid; i < DD * 16; i += 512)
                Ws[i] = g_WD[(size_t)(i >> 4) * NG + bx * 16 + (i & 15)];
            bias = *(const float4 *)&g_biasd[bx * 16 + 4 * dl];
            __syncthreads();
        }

        // ---- read-wait: this warp's 8 producer blocks finished step st-1
        if (lane < 8) {
            while (g_wflag[(8 * w + lane) * 32] < (unsigned)st) { }
        }
        __syncwarp();

        const float4 *hb = (const float4 *)g_hT4[(st + 3) & 3] + aoff;  // h_{st-1}
        float *hw = g_hT4[st & 3];                                      // h_st

        // prefetch xg for this thread's cell — consumed after the GEMM
        float4 xa = make_float4(0.f, 0.f, 0.f, 0.f);
        if (enc)
            xa = __ldcg((const float4 *)&g_xg[((size_t)st * BB + mo) * NG + bx * 16 + 4 * dl]);

        // ---- GEMM over this warp's k-slice (R10 engine)
        float2 acc[4][8];
#pragma unroll
        for (int i = 0; i < 4; ++i)
#pragma unroll
            for (int c = 0; c < 8; ++c) acc[i][c] = make_float2(0.f, 0.f);

        float4 pf[4];
#pragma unroll
        for (int j = 0; j < 4; ++j)
            pf[j] = __ldcg(hb + j * 32);

        const float4 *wp = (const float4 *)&Ws[k0 * 16];
#pragma unroll 4
        for (int k = 0; k < 32; ++k) {
            float4 hv = pf[k & 3];
            pf[k & 3] = __ldcg(hb + ((k + 4) & 31) * 32);  // wrap: tail reloads, unused data
            const float4 w0 = wp[k * 4 + 0], w1 = wp[k * 4 + 1];
            const float4 w2 = wp[k * 4 + 2], w3 = wp[k * 4 + 3];
            const float av[4] = {hv.x, hv.y, hv.z, hv.w};
#pragma unroll
            for (int i = 0; i < 4; ++i) {
                float2 a = make_float2(av[i], av[i]);
                fma2(acc[i][0], a, make_float2(w0.x, w0.y));
                fma2(acc[i][1], a, make_float2(w0.z, w0.w));
                fma2(acc[i][2], a, make_float2(w1.x, w1.y));
                fma2(acc[i][3], a, make_float2(w1.z, w1.w));
                fma2(acc[i][4], a, make_float2(w2.x, w2.y));
                fma2(acc[i][5], a, make_float2(w2.z, w2.w));
                fma2(acc[i][6], a, make_float2(w3.x, w3.y));
                fma2(acc[i][7], a, make_float2(w3.z, w3.w));
            }
        }

        // ---- store partials (swizzled so reduce reads stay spread)
#pragma unroll
        for (int i = 0; i < 4; ++i) {
#pragma unroll
            for (int c4 = 0; c4 < 4; ++c4) {
                float4 v = make_float4(acc[i][2 * c4].x,     acc[i][2 * c4].y,
                                       acc[i][2 * c4 + 1].x, acc[i][2 * c4 + 1].y);
                *(float4 *)(stp[i] + ((c4 ^ ssw[i]) * 4)) = v;
            }
        }
        __syncthreads();                          // all h-reads + partials done
        if (tid == 0) g_gdone[bx * 32] = (unsigned)(st + 1);

        // ---- write-wait: all blocks past GEMM of step st-3 (buffer st&3 free)
        if (st >= 3) {
            unsigned wt = (unsigned)(st - 2);
#pragma unroll
            for (int p = 0; p < 4; ++p) {
                while (g_gdone[(lane + p * 32) * 32] < wt) { }
            }
        }
        __syncwarp();

        // ---- reduce 16 partials + cell update (one cell per thread)
        {
            float4 s = make_float4(0.f, 0.f, 0.f, 0.f);
#pragma unroll
            for (int ww = 0; ww < 16; ++ww) {
                const float4 v = *(const float4 *)(rptr + ww * 2048);
                s.x += v.x; s.y += v.y; s.z += v.z; s.w += v.w;
            }
            float gi = s.x + bias.x + xa.x;
            float gf = s.y + bias.y + xa.y;
            float gg = s.z + bias.z + xa.z;
            float go = s.w + bias.w + xa.w;
            float cn = sigm(gf) * cst + sigm(gi) * tanhf(gg);
            cst = cn;
            float h0 = sigm(go) * tanhf(cn);
            hw[(4 * bx + dl) * BB + mo] = h0;
            if (!enc)
                g_hist[(size_t)(st - SEQ + 1) * BB * DD + (size_t)mo * DD + 4 * bx + dl] = h0;
            else if (st == SEQ - 1)
                g_hist[(size_t)mo * DD + 4 * bx + dl] = h0;
        }
        __threadfence();                          // publish h stores
        __syncthreads();                          // all threads fenced; also guards partials reuse
        if (tid == 0) g_wflag[bx * 32] = (unsigned)(st + 1);
    }
}

// ==================== batched output projection ====================
__global__ __launch_bounds__(256) void final_pred(const float *__restrict__ bp,
                                                  float *__restrict__ out)
{
    __shared__ float As[2][8 * 132];
    __shared__ float Bs[2][8 * 128];
    const int t = blockIdx.y, ebase = blockIdx.x * 128, tid = threadIdx.x;
    const int tm8 = (tid >> 4) * 8, tn8 = (tid & 15) * 8;
    const float *A = g_hist + (size_t)t * BB * DD;

    Slots s; make_slots(s, tid);
    float2 acc[8][4];
#pragma unroll
    for (int r = 0; r < 8; ++r)
#pragma unroll
        for (int c = 0; c < 4; ++c) acc[r][c] = make_float2(0.f, 0.f);

    float ar[4], br[4];
    auto load = [&](int kb) {
#pragma unroll
        for (int p = 0; p < 4; ++p) {
            ar[p] = A[(size_t)s.mmp[p] * DD + kb + s.klp[p]];
            br[p] = g_WpT2[(size_t)(kb + s.kwp[p]) * EPAD + ebase + s.nlp[p]];
        }
    };

    int buf = 0;
    load(0);
    stage(s, ar, br, As[0], Bs[0]);
    __syncthreads();
#pragma unroll 1
    for (int c8 = 0; c8 < 64; ++c8) {
        if (c8 < 63) load((c8 + 1) * 8);
        mma8(acc, As[buf], Bs[buf], tm8, tn8);
        if (c8 < 63) { stage(s, ar, br, As[buf ^ 1], Bs[buf ^ 1]); __syncthreads(); buf ^= 1; }
    }
#pragma unroll
    for (int r = 0; r < 8; ++r) {
        int b = tm8 + r;
        float *orow = out + ((size_t)b * PRED + t) * ENC;
        float vals[8] = {acc[r][0].x, acc[r][0].y, acc[r][1].x, acc[r][1].y,
                         acc[r][2].x, acc[r][2].y, acc[r][3].x, acc[r][3].y};
#pragma unroll
        for (int c = 0; c < 8; ++c) {
            int e = ebase + tn8 + c;
            if (e < ENC) orow[e] = vals[c] + bp[e];
        }
    }
}

extern "C" void kernel_launch(void *const *d_in, const int *in_sizes, int n_in,
                              void *d_out, int out_size)
{
    const float *x   = (const float *)d_in[0];
    const float *Wih = (const float *)d_in[1];
    const float *Whh = (const float *)d_in[2];
    const float *bih = (const float *)d_in[3];
    const float *bhh = (const float *)d_in[4];
    const float *Wp  = (const float *)d_in[5];
    const float *bp  = (const float *)d_in[6];
    float *out = (float *)d_out;

    cudaFuncSetAttribute(lstm_persistent,
                         cudaFuncAttributeMaxDynamicSharedMemorySize, LSTM_SMEM);

    prepA<<<4096, 256>>>(Wih, Whh, bih, bhh, Wp);
    prepB<<<NG, 128>>>(Wih, Whh, bp);
    xg_proj<<<dim3(16, SEQ), 256>>>(x);
    lstm_persistent<<<NBLK, 512, LSTM_SMEM>>>();
    final_pred<<<dim3(3, PRED), 256>>>(bp, out);
}

// round 15
// speedup vs baseline: 1.1451x; 1.1451x over previous
#include <cuda_runtime.h>
#include <cuda_bf16.h>
#include <cstdint>
#include <cstddef>

#define BB   128
#define SEQ  720
#define PRED 336
#define ENC  321
#define DD   512
#define NG   2048           // 4*D
#define XSTR (SEQ*ENC)
#define KXP  328            // ENC padded to 41*8
#define EPAD 384            // ENC padded for W_pred^T tiles
#define NBLK 128            // persistent grid

// A tiles: pad 512B tile to 528B to spread smem banks
#define KT_STRIDE 528
#define MT_STRIDE (16 * KT_STRIDE)        // 8448
#define TERM_STRIDE (8 * MT_STRIDE)       // 67584
#define ABUF_BYTES (2 * TERM_STRIDE)      // 135168
#define BFRAG_BYTES 32768
#define LSTM_SMEM (ABUF_BYTES + BFRAG_BYTES + 1024)

// -------- persistent device scratch --------
__device__ float g_WX  [KXP * NG];        // Wih^T gate-interleaved [k][n], n=d*4+gate
__device__ float g_WE  [DD * NG];         // Whh^T gate-interleaved [k][n] fp32
__device__ float g_WD  [DD * NG];         // decoder (Wih@Wp + Whh)^T gate-interleaved
__device__ float g_WpT2[DD * EPAD];       // W_pred^T padded [k][e]
__device__ float g_bias [NG];
__device__ float g_biasd[NG];
__device__ unsigned short g_hbf[2][2][BB * DD];   // ping-pong h, bf16 {hi,lo}, [m][k] row-major
__device__ float g_xg[(size_t)SEQ * BB * NG];     // precomputed x projections
__device__ float g_hist[(size_t)PRED * BB * DD];  // decoder h_t log ([t][m][dim])

__device__ volatile unsigned g_flag[NBLK * 32];   // barrier flags, 128 B apart

// -------- helpers --------
__device__ __forceinline__ void fma2(float2 &d, float2 a, float2 b) {
    unsigned long long &du = reinterpret_cast<unsigned long long &>(d);
    unsigned long long au  = reinterpret_cast<unsigned long long &>(a);
    unsigned long long bu  = reinterpret_cast<unsigned long long &>(b);
    asm("fma.rn.f32x2 %0, %1, %2, %0;" : "+l"(du) : "l"(au), "l"(bu));
}
__device__ __forceinline__ float sigm(float x) { return 1.f / (1.f + __expf(-x)); }
__device__ __forceinline__ uint32_t s2u(const void *p) {
    uint32_t a;
    asm("{ .reg .u64 t; cvta.to.shared.u64 t, %1; cvt.u32.u64 %0, t; }" : "=r"(a) : "l"(p));
    return a;
}
__device__ __forceinline__ unsigned short f2bf(float x) {
    unsigned short u; asm("cvt.rn.bf16.f32 %0, %1;" : "=h"(u) : "f"(x)); return u;
}
__device__ __forceinline__ float bf2f(unsigned short u) {
    float f; asm("cvt.f32.bf16 %0, %1;" : "=f"(f) : "h"(u)); return f;
}
__device__ __forceinline__ void ldmx4(uint32_t &r0, uint32_t &r1, uint32_t &r2, uint32_t &r3,
                                      uint32_t addr) {
    asm volatile("ldmatrix.sync.aligned.m8n8.x4.shared.b16 {%0,%1,%2,%3}, [%4];"
                 : "=r"(r0), "=r"(r1), "=r"(r2), "=r"(r3) : "r"(addr));
}
__device__ __forceinline__ void mma16816(float &d0, float &d1, float &d2, float &d3,
                                         uint32_t a0, uint32_t a1, uint32_t a2, uint32_t a3,
                                         uint32_t b0, uint32_t b1) {
    asm volatile(
        "mma.sync.aligned.m16n8k16.row.col.f32.bf16.bf16.f32 "
        "{%0,%1,%2,%3}, {%4,%5,%6,%7}, {%8,%9}, {%0,%1,%2,%3};"
        : "+f"(d0), "+f"(d1), "+f"(d2), "+f"(d3)
        : "r"(a0), "r"(a1), "r"(a2), "r"(a3), "r"(b0), "r"(b1));
}

// -------- flag-array grid barrier --------
__device__ __forceinline__ void grid_sync_flag(unsigned target) {
    __threadfence();
    __syncthreads();
    if (threadIdx.x == 0) g_flag[blockIdx.x * 32] = target;
    if (threadIdx.x < NBLK) {
        while (g_flag[threadIdx.x * 32] < target) { }
    }
    __syncthreads();
}

// -------- GEMM micro-kernel pieces (xg_proj / final_pred) --------
struct Slots { int klp[4], mmp[4], kwp[4], nlp[4]; };

__device__ __forceinline__ void make_slots(Slots &s, int tid) {
#pragma unroll
    for (int p = 0; p < 4; ++p) {
        int lin = tid + p * 256;
        s.klp[p] = lin & 7;   s.mmp[p] = lin >> 3;
        s.nlp[p] = lin & 127; s.kwp[p] = lin >> 7;
    }
}
__device__ __forceinline__ void stage(const Slots &s, const float *ur, const float *wr,
                                      float *U, float *W) {
#pragma unroll
    for (int p = 0; p < 4; ++p) {
        U[s.klp[p] * 132 + s.mmp[p]] = ur[p];
        W[s.kwp[p] * 128 + s.nlp[p]] = wr[p];
    }
}
__device__ __forceinline__ void mma8(float2 acc[8][4], const float *U, const float *W,
                                     int tm8, int tn8) {
#pragma unroll
    for (int q = 0; q < 8; ++q) {
        const float4 a0 = *(const float4 *)&U[q * 132 + tm8];
        const float4 a1 = *(const float4 *)&U[q * 132 + tm8 + 4];
        const float4 b0 = *(const float4 *)&W[q * 128 + tn8];
        const float4 b1 = *(const float4 *)&W[q * 128 + tn8 + 4];
        float  av[8] = {a0.x, a0.y, a0.z, a0.w, a1.x, a1.y, a1.z, a1.w};
        float2 bv[4] = {make_float2(b0.x, b0.y), make_float2(b0.z, b0.w),
                        make_float2(b1.x, b1.y), make_float2(b1.z, b1.w)};
#pragma unroll
        for (int r = 0; r < 8; ++r) {
            float2 ad = make_float2(av[r], av[r]);
#pragma unroll
            for (int c = 0; c < 4; ++c) fma2(acc[r][c], ad, bv[c]);
        }
    }
}

// ==================== prep kernels ====================
__global__ void prepA(const float *__restrict__ Wih, const float *__restrict__ Whh,
                      const float *__restrict__ bih, const float *__restrict__ bhh,
                      const float *__restrict__ Wp)
{
    int idx = blockIdx.x * 256 + threadIdx.x;
    if (idx < KXP * NG) {
        int k = idx / NG, n = idx - k * NG, d = n >> 2, gate = n & 3, j = gate * DD + d;
        g_WX[idx] = (k < ENC) ? Wih[(size_t)j * ENC + k] : 0.f;
    }
    if (idx < DD * NG) {
        int k = idx / NG, n = idx - k * NG, d = n >> 2, gate = n & 3, j = gate * DD + d;
        g_WE[idx] = Whh[(size_t)j * DD + k];
    }
    if (idx < DD * EPAD) {
        int k = idx / EPAD, e = idx - k * EPAD;
        g_WpT2[idx] = (e < ENC) ? Wp[(size_t)e * DD + k] : 0.f;
    }
    if (idx < NG) {
        int j = idx, n = (j & 511) * 4 + (j >> 9);
        g_bias[n] = bih[j] + bhh[j];
    }
    if (idx < 65536) ((unsigned long long *)g_hbf)[idx] = 0ULL;   // zero h bf16 buffers
    if (idx < NBLK * 32) g_flag[idx] = 0;                         // graph-replay safe
}

__global__ void prepB(const float *__restrict__ Wih, const float *__restrict__ Whh,
                      const float *__restrict__ bp)
{
    __shared__ float sW[EPAD];
    __shared__ float red[128];
    const int j = blockIdx.x, tid = threadIdx.x;
    for (int e = tid; e < EPAD; e += 128) sW[e] = (e < ENC) ? Wih[(size_t)j * ENC + e] : 0.f;
    __syncthreads();
    const int d = j & 511, gate = j >> 9, n = d * 4 + gate;
    for (int k = tid; k < DD; k += 128) {
        float a0 = 0.f, a1 = 0.f, a2 = 0.f, a3 = 0.f;
        const float *wr = &g_WpT2[(size_t)k * EPAD];
        for (int e = 0; e < EPAD; e += 4) {
            const float4 wv = *(const float4 *)&wr[e];
            const float4 sv = *(const float4 *)&sW[e];
            a0 += sv.x * wv.x; a1 += sv.y * wv.y; a2 += sv.z * wv.z; a3 += sv.w * wv.w;
        }
        g_WD[(size_t)k * NG + n] = (a0 + a1) + (a2 + a3) + Whh[(size_t)j * DD + k];
    }
    float p = 0.f;
    for (int e = tid; e < ENC; e += 128) p += sW[e] * bp[e];
    red[tid] = p; __syncthreads();
    for (int off = 64; off; off >>= 1) { if (tid < off) red[tid] += red[tid + off]; __syncthreads(); }
    if (tid == 0) g_biasd[n] = g_bias[n] + red[0];
}

// ==================== parallel input projection: xg[t][b][n] ====================
__global__ __launch_bounds__(256) void xg_proj(const float *__restrict__ x)
{
    __shared__ float Us[2][8 * 132];
    __shared__ float Ws[2][8 * 128];
    const int t = blockIdx.y, nbase = blockIdx.x * 128, tid = threadIdx.x;
    const int tm8 = (tid >> 4) * 8, tn8 = (tid & 15) * 8;
    const float *xbase = x + (size_t)t * ENC;

    Slots s; make_slots(s, tid);
    float2 acc[8][4];
#pragma unroll
    for (int r = 0; r < 8; ++r)
#pragma unroll
        for (int c = 0; c < 4; ++c) acc[r][c] = make_float2(0.f, 0.f);

    float ur[4], wr[4];
    auto load = [&](int kb) {
#pragma unroll
        for (int p = 0; p < 4; ++p) {
            int k = kb + s.klp[p];
            ur[p] = (k < ENC) ? __ldg(&xbase[(size_t)s.mmp[p] * XSTR + k]) : 0.f;
            wr[p] = g_WX[(size_t)(kb + s.kwp[p]) * NG + nbase + s.nlp[p]];
        }
    };

    int buf = 0;
    load(0);
    stage(s, ur, wr, Us[0], Ws[0]);
    __syncthreads();
#pragma unroll 1
    for (int c8 = 0; c8 < 41; ++c8) {
        if (c8 < 40) load((c8 + 1) * 8);
        mma8(acc, Us[buf], Ws[buf], tm8, tn8);
        if (c8 < 40) { stage(s, ur, wr, Us[buf ^ 1], Ws[buf ^ 1]); __syncthreads(); buf ^= 1; }
    }
#pragma unroll
    for (int r = 0; r < 8; ++r) {
        float *dst = &g_xg[((size_t)t * BB + tm8 + r) * NG + nbase + tn8];
        *(float4 *)dst       = make_float4(acc[r][0].x, acc[r][0].y, acc[r][1].x, acc[r][1].y);
        *(float4 *)(dst + 4) = make_float4(acc[r][2].x, acc[r][2].y, acc[r][3].x, acc[r][3].y);
    }
}

// ==================== persistent recurrent kernel (mma.sync HMMA) ====================
// 128 blocks x 512 threads (16 warps). Block bx owns gate-cols [16bx,16bx+16)
// == dims [4bx,4bx+4). gates[128m x 16n] = h[128m x 512k] @ Wstrip^T, bf16
// 3-product hi/lo split, fp32 accum in registers. Warp w = (m-tile w&7,
// n-half w>>3) owns one m16n8 output -> full-K in-register accumulation.
// A staged per half-K into swizzled 16x16 tiles (ldmatrix.x4); B fragments
// precomputed per phase into fragment-layout smem. Epilogue: shfl-pair gate
// exchange, one cell per thread, c in register. One flag barrier per step.
__global__ __launch_bounds__(512, 1) void lstm_persistent()
{
    extern __shared__ char dsm[];
    const int tid = threadIdx.x, bx = blockIdx.x;
    const int wid = tid >> 5, lane = tid & 31;
    const int mt = wid & 7, nh = wid >> 3;

    uint32_t raw = s2u(dsm);
    uint32_t abase = (raw + 1023u) & ~1023u;
    char *Abuf  = dsm + (abase - raw);
    char *Bfrag = Abuf + ABUF_BYTES;
    const uint32_t AbufU  = abase;
    const uint32_t BfragU = abase + ABUF_BYTES;

    // ldmatrix per-lane base address (term 0); kt adds kt*KT_STRIDE, term adds TERM_STRIDE
    const int lrow = lane & 15, lchunk = lane >> 4;
    const uint32_t aAddr0 = AbufU + mt * MT_STRIDE + lrow * 32
                          + ((lchunk ^ ((lrow >> 2) & 1)) * 16);
    // B fragment read base for this warp
    const uint32_t bAddr0 = BfragU + nh * 16384 + lane * 8;

    // epilogue cell mapping
    const int g = lane >> 2, tig = lane & 3;
    const int dl = nh * 2 + (tig >> 1);
    const bool odd = (tig & 1);
    const int mcell = 16 * mt + g + (odd ? 8 : 0);
    const int dcell = 4 * bx + dl;

    // stage B fragments (bf16 hi/lo, PTX m16n8k16 B layout) from fp32 strip
    auto stageB = [&](const float *Wsrc) {
#pragma unroll 1
        for (int it = 0; it < 8; ++it) {
            int slot = tid + it * 512;           // 4096 slots
            int sl = slot & 31, sterm = (slot >> 5) & 1;
            int skt = (slot >> 6) & 31, snh = slot >> 11;
            int n = snh * 8 + (sl >> 2);
            ushort4 v;
            unsigned short e[4];
#pragma unroll
            for (int ei = 0; ei < 4; ++ei) {
                int k = skt * 16 + 2 * (sl & 3) + (ei & 1) + ((ei >> 1) * 8);
                float wv = Wsrc[(size_t)k * NG + bx * 16 + n];
                unsigned short hi = f2bf(wv);
                e[ei] = sterm ? f2bf(wv - bf2f(hi)) : hi;
            }
            v.x = e[0]; v.y = e[1]; v.z = e[2]; v.w = e[3];
            *(ushort4 *)(Bfrag + snh * 16384 + skt * 512 + sterm * 256 + sl * 8) = v;
        }
    };

    float4 bias = *(const float4 *)&g_bias[bx * 16 + 4 * dl];
    float cst = 0.f;
    stageB(g_WE);
    __syncthreads();

    for (int st = 0; st < SEQ + PRED - 1; ++st) {
        const bool enc = (st < SEQ);
        if (st == SEQ) {
            stageB(g_WD);
            bias = *(const float4 *)&g_biasd[bx * 16 + 4 * dl];
            __syncthreads();
        }
        const int rd = st & 1, wp = rd ^ 1;

        // xg prefetch (encoder only)
        float4 xa = make_float4(0.f, 0.f, 0.f, 0.f);
        if (enc)
            xa = __ldcg((const float4 *)
                &g_xg[((size_t)st * BB + mcell) * NG + bx * 16 + 4 * dl]);

        float d0 = 0.f, d1 = 0.f, d2 = 0.f, d3 = 0.f;

#pragma unroll 1
        for (int hf = 0; hf < 2; ++hf) {
            // ---- stage A half (hi+lo) into swizzled 16x16 tiles
#pragma unroll
            for (int p = 0; p < 16; ++p) {
                int ci = tid + p * 512;
                int term = ci >> 12, rem = ci & 4095;
                int kc = rem & 31, m = rem >> 5;
                uint4 v = __ldcg((const uint4 *)&g_hbf[rd][term][m * DD + hf * 256 + kc * 8]);
                int row = m & 15, mtt = m >> 4, kt = kc >> 1, ch = kc & 1;
                *(uint4 *)(Abuf + term * TERM_STRIDE + mtt * MT_STRIDE + kt * KT_STRIDE
                           + row * 32 + ((ch ^ ((row >> 2) & 1)) * 16)) = v;
            }
            __syncthreads();

            // ---- 16 k-tiles of HMMA
#pragma unroll 2
            for (int kt = 0; kt < 16; ++kt) {
                uint32_t aAddr = aAddr0 + kt * KT_STRIDE;
                uint32_t ah0, ah1, ah2, ah3, al0, al1, al2, al3;
                ldmx4(ah0, ah1, ah2, ah3, aAddr);
                ldmx4(al0, al1, al2, al3, aAddr + TERM_STRIDE);
                int ktg = hf * 16 + kt;
                uint2 bh = *(const uint2 *)(Bfrag + nh * 16384 + ktg * 512 + lane * 8);
                uint2 bl = *(const uint2 *)(Bfrag + nh * 16384 + ktg * 512 + 256 + lane * 8);
                mma16816(d0, d1, d2, d3, ah0, ah1, ah2, ah3, bh.x, bh.y);
                mma16816(d0, d1, d2, d3, ah0, ah1, ah2, ah3, bl.x, bl.y);
                mma16816(d0, d1, d2, d3, al0, al1, al2, al3, bh.x, bh.y);
            }
            __syncthreads();   // A buffer reused by next half / next step
        }

        // ---- epilogue: pair-exchange gates, one cell per thread
        {
            // even (tig&1==0) holds (i,f) rows g,g+8; odd holds (g,o) rows g,g+8.
            // even keeps row g, odd keeps row g+8; exchange the complementary pair.
            float sx = odd ? d0 : d2;
            float sy = odd ? d1 : d3;
            float rx = __shfl_xor_sync(0xffffffffu, sx, 1, 32);
            float ry = __shfl_xor_sync(0xffffffffu, sy, 1, 32);
            float gi, gf, gg, go;
            if (!odd) { gi = d0; gf = d1; gg = rx; go = ry; }
            else      { gi = rx; gf = ry; gg = d2; go = d3; }

            gi += bias.x + xa.x;
            gf += bias.y + xa.y;
            gg += bias.z + xa.z;
            go += bias.w + xa.w;
            float cn = sigm(gf) * cst + sigm(gi) * tanhf(gg);
            cst = cn;
            float h0 = sigm(go) * tanhf(cn);

            unsigned short hi = f2bf(h0);
            unsigned short lo = f2bf(h0 - bf2f(hi));
            g_hbf[wp][0][mcell * DD + dcell] = hi;
            g_hbf[wp][1][mcell * DD + dcell] = lo;

            if (!enc)
                g_hist[(size_t)(st - SEQ + 1) * BB * DD + (size_t)mcell * DD + dcell] = h0;
            else if (st == SEQ - 1)
                g_hist[(size_t)mcell * DD + dcell] = h0;
        }
        grid_sync_flag((unsigned)(st + 1));
    }
}

// ==================== batched output projection ====================
__global__ __launch_bounds__(256) void final_pred(const float *__restrict__ bp,
                                                  float *__restrict__ out)
{
    __shared__ float As[2][8 * 132];
    __shared__ float Bs[2][8 * 128];
    const int t = blockIdx.y, ebase = blockIdx.x * 128, tid = threadIdx.x;
    const int tm8 = (tid >> 4) * 8, tn8 = (tid & 15) * 8;
    const float *A = g_hist + (size_t)t * BB * DD;

    Slots s; make_slots(s, tid);
    float2 acc[8][4];
#pragma unroll
    for (int r = 0; r < 8; ++r)
#pragma unroll
        for (int c = 0; c < 4; ++c) acc[r][c] = make_float2(0.f, 0.f);

    float ar[4], br[4];
    auto load = [&](int kb) {
#pragma unroll
        for (int p = 0; p < 4; ++p) {
            ar[p] = A[(size_t)s.mmp[p] * DD + kb + s.klp[p]];
            br[p] = g_WpT2[(size_t)(kb + s.kwp[p]) * EPAD + ebase + s.nlp[p]];
        }
    };

    int buf = 0;
    load(0);
    stage(s, ar, br, As[0], Bs[0]);
    __syncthreads();
#pragma unroll 1
    for (int c8 = 0; c8 < 64; ++c8) {
        if (c8 < 63) load((c8 + 1) * 8);
        mma8(acc, As[buf], Bs[buf], tm8, tn8);
        if (c8 < 63) { stage(s, ar, br, As[buf ^ 1], Bs[buf ^ 1]); __syncthreads(); buf ^= 1; }
    }
#pragma unroll
    for (int r = 0; r < 8; ++r) {
        int b = tm8 + r;
        float *orow = out + ((size_t)b * PRED + t) * ENC;
        float vals[8] = {acc[r][0].x, acc[r][0].y, acc[r][1].x, acc[r][1].y,
                         acc[r][2].x, acc[r][2].y, acc[r][3].x, acc[r][3].y};
#pragma unroll
        for (int c = 0; c < 8; ++c) {
            int e = ebase + tn8 + c;
            if (e < ENC) orow[e] = vals[c] + bp[e];
        }
    }
}

extern "C" void kernel_launch(void *const *d_in, const int *in_sizes, int n_in,
                              void *d_out, int out_size)
{
    const float *x   = (const float *)d_in[0];
    const float *Wih = (const float *)d_in[1];
    const float *Whh = (const float *)d_in[2];
    const float *bih = (const float *)d_in[3];
    const float *bhh = (const float *)d_in[4];
    const float *Wp  = (const float *)d_in[5];
    const float *bp  = (const float *)d_in[6];
    float *out = (float *)d_out;

    cudaFuncSetAttribute(lstm_persistent,
                         cudaFuncAttributeMaxDynamicSharedMemorySize, LSTM_SMEM);

    prepA<<<4096, 256>>>(Wih, Whh, bih, bhh, Wp);
    prepB<<<NG, 128>>>(Wih, Whh, bp);
    xg_proj<<<dim3(16, SEQ), 256>>>(x);
    lstm_persistent<<<NBLK, 512, LSTM_SMEM>>>();
    final_pred<<<dim3(3, PRED), 256>>>(bp, out);
}